// round 8
// baseline (speedup 1.0000x reference)
#include <cuda_runtime.h>
#include <math.h>

#define MAX_EDGES 100000
#define MAX_PART  256

__device__ float g_scores[MAX_EDGES];
__device__ float g_pmax[MAX_PART];
__device__ int   g_pidx[MAX_PART];
__device__ float g_psum[MAX_PART];
__device__ unsigned int g_ticket;   // zero-init; last block resets each run

// ---------------------------------------------------------------------------
// Kernel 1: s[e] = dot(edge_emb[e,:256], W)   [known-best: ~18.5us, 32 regs]
// One warp per TWO edges; 4 independent LDG.128 per lane.
// ---------------------------------------------------------------------------
__global__ void __launch_bounds__(256) score_kernel(
        const float* __restrict__ emb,
        const float* __restrict__ W,
        float* __restrict__ s,
        int n_edges) {
    int warp = (blockIdx.x * blockDim.x + threadIdx.x) >> 5;
    int lane = threadIdx.x & 31;
    int e0 = warp * 2;

    if (e0 < n_edges) {
        const float4* w = reinterpret_cast<const float4*>(W);
        float4 w0 = __ldg(&w[lane * 2]);
        float4 w1 = __ldg(&w[lane * 2 + 1]);

        const float4* p0 = reinterpret_cast<const float4*>(emb + (size_t)e0 * 256);
        const float4* p1 = p0 + 64;

        float4 a0 = p0[lane * 2];
        float4 a1 = p0[lane * 2 + 1];
        float4 b0 = p1[lane * 2];
        float4 b1 = p1[lane * 2 + 1];

        float accA = a0.x*w0.x + a0.y*w0.y + a0.z*w0.z + a0.w*w0.w
                   + a1.x*w1.x + a1.y*w1.y + a1.z*w1.z + a1.w*w1.w;
        float accB = b0.x*w0.x + b0.y*w0.y + b0.z*w0.z + b0.w*w0.w
                   + b1.x*w1.x + b1.y*w1.y + b1.z*w1.z + b1.w*w1.w;

        #pragma unroll
        for (int o = 16; o; o >>= 1) {
            accA += __shfl_xor_sync(0xFFFFFFFFu, accA, o);
            accB += __shfl_xor_sync(0xFFFFFFFFu, accB, o);
        }

        if (lane == 0) {
            s[e0] = accA;
            if (e0 + 1 < n_edges) s[e0 + 1] = accB;
        }
    }

    cudaTriggerProgrammaticLaunchCompletion();
}

// ---------------------------------------------------------------------------
// Kernel 2 (fused, PDL secondary): logits + flash-softmax partials; the last
// ticket block finalizes (p, logprob, z[p]).
// z[p] is a FIXED 16-iteration unrolled loop with unconditional loads
// (all paths entries are valid edge ids) and predicated accumulate, so all
// 16 loads are in flight at once instead of a serial latency chain.
// out: [0]=p, [1]=logprob, [2..257]=z[p]
// ---------------------------------------------------------------------------
__global__ void __launch_bounds__(256) paths_fused_kernel(
        const int* __restrict__ paths,
        const int* __restrict__ path_lens,
        const int* __restrict__ path_mask,
        const float* __restrict__ s,
        const float* __restrict__ b,
        const float* __restrict__ emb,
        int n_paths, int max_len, int n_blocks,
        float* __restrict__ out) {
    __shared__ float smax[256];
    __shared__ int   sidx[256];
    __shared__ float ssum[256];
    __shared__ int   s_is_last;

    int t = threadIdx.x;
    int i = blockIdx.x * 256 + t;
    bool live = (i < n_paths);

    // ---- preamble: score-independent loads (overlap primary via PDL) ----
    int4 r0 = make_int4(0,0,0,0), r1 = r0, r2 = r0, r3 = r0;
    int  my_len = 1, my_mask = 0;
    float bias = 0.0f;
    if (live) {
        const int4* row = reinterpret_cast<const int4*>(paths + (size_t)i * max_len);
        r0 = row[0]; r1 = row[1]; r2 = row[2]; r3 = row[3];
        my_len  = path_lens[i] + 1;
        my_mask = path_mask[i];
        bias    = b[0];
    }

    cudaGridDependencySynchronize();   // wait for scores

    // ---- per-thread logit ----
    float logit = -INFINITY;
    int   idx   = 0x7FFFFFFF;
    if (live) {
        int e[16] = { r0.x, r0.y, r0.z, r0.w, r1.x, r1.y, r1.z, r1.w,
                      r2.x, r2.y, r2.z, r2.w, r3.x, r3.y, r3.z, r3.w };
        float sum = 0.0f;
        #pragma unroll
        for (int j = 0; j < 16; ++j) {
            float v = s[e[j]];                 // unconditional, independent
            sum += (j < my_len) ? v : 0.0f;
        }
        logit = sum / (float)my_len + bias;
        if (my_mask == 0) logit = -1e9f;
        idx = i;
    }

    // ---- block argmax (first-occurrence tiebreak) ----
    smax[t] = logit; sidx[t] = idx;
    __syncthreads();
    #pragma unroll
    for (int o = 128; o; o >>= 1) {
        if (t < o) {
            float v = smax[t + o]; int j = sidx[t + o];
            if (v > smax[t] || (v == smax[t] && j < sidx[t])) {
                smax[t] = v; sidx[t] = j;
            }
        }
        __syncthreads();
    }
    float bm = smax[0];

    // ---- block sumexp vs block max ----
    float es = live ? expf(logit - bm) : 0.0f;
    ssum[t] = es;
    __syncthreads();
    #pragma unroll
    for (int o = 128; o; o >>= 1) {
        if (t < o) ssum[t] += ssum[t + o];
        __syncthreads();
    }

    // ---- publish partials, draw ticket ----
    if (t == 0) {
        g_pmax[blockIdx.x] = bm;
        g_pidx[blockIdx.x] = sidx[0];
        g_psum[blockIdx.x] = ssum[0];
        __threadfence();
        unsigned rank = atomicAdd(&g_ticket, 1u);
        s_is_last = (rank == (unsigned)(n_blocks - 1));
    }
    __syncthreads();
    if (!s_is_last) return;

    // ===== last block: finalize =====
    __threadfence();

    float m = (t < n_blocks) ? g_pmax[t] : -INFINITY;
    int   j = (t < n_blocks) ? g_pidx[t] : 0x7FFFFFFF;
    smax[t] = m; sidx[t] = j;
    __syncthreads();
    #pragma unroll
    for (int o = 128; o; o >>= 1) {
        if (t < o) {
            float v = smax[t + o]; int k = sidx[t + o];
            if (v > smax[t] || (v == smax[t] && k < sidx[t])) {
                smax[t] = v; sidx[t] = k;
            }
        }
        __syncthreads();
    }
    float M = smax[0];
    int   p = sidx[0];
    __syncthreads();

    float e2 = (t < n_blocks) ? g_psum[t] * expf(g_pmax[t] - M) : 0.0f;
    ssum[t] = e2;
    __syncthreads();
    #pragma unroll
    for (int o = 128; o; o >>= 1) {
        if (t < o) ssum[t] += ssum[t + o];
        __syncthreads();
    }

    if (t == 0) {
        out[0] = (float)p;
        out[1] = -logf(ssum[0]);   // logits[p] == M
        g_ticket = 0;              // reset for next graph replay
    }

    // ---- z[p]: fixed-unroll ragged mean, all 16 loads in flight ----
    {
        int len = path_lens[p] + 1;
        const int4* row4 = reinterpret_cast<const int4*>(paths + (size_t)p * max_len);
        int4 q0 = row4[0], q1 = row4[1], q2 = row4[2], q3 = row4[3];
        int e[16] = { q0.x, q0.y, q0.z, q0.w, q1.x, q1.y, q1.z, q1.w,
                      q2.x, q2.y, q2.z, q2.w, q3.x, q3.y, q3.z, q3.w };
        float acc = 0.0f;
        #pragma unroll
        for (int k = 0; k < 16; ++k) {
            float v = emb[(size_t)e[k] * 256 + t];   // unconditional, independent
            acc += (k < len) ? v : 0.0f;
        }
        out[2 + t] = acc / (float)len;
    }
}

// ---------------------------------------------------------------------------
// Launch
// Inputs: edge_emb f32[100000,256], paths i32[20000,16], path_lens i32[20000],
//         path_mask i32[20000], W f32[1,256], b f32[1], deterministic i32[1]
// ---------------------------------------------------------------------------
extern "C" void kernel_launch(void* const* d_in, const int* in_sizes, int n_in,
                              void* d_out, int out_size) {
    const float* edge_emb  = (const float*)d_in[0];
    const int*   paths     = (const int*)d_in[1];
    const int*   path_lens = (const int*)d_in[2];
    const int*   path_mask = (const int*)d_in[3];
    const float* W         = (const float*)d_in[4];
    const float* b         = (const float*)d_in[5];

    int hidden  = in_sizes[4];              // 256
    int n_edges = in_sizes[0] / hidden;     // 100000
    int n_paths = in_sizes[2];              // 20000
    int max_len = in_sizes[1] / n_paths;    // 16

    float* out = (float*)d_out;

    float* scores; cudaGetSymbolAddress((void**)&scores, g_scores);

    // K1: 2 edges per warp, 8 warps per block (known-best config)
    {
        int edges_per_block = 16;
        int blocks = (n_edges + edges_per_block - 1) / edges_per_block;
        score_kernel<<<blocks, 256>>>(edge_emb, W, scores, n_edges);
    }

    // K2 fused, PDL secondary
    int nb2 = (n_paths + 255) / 256;        // 79

    cudaLaunchConfig_t cfg = {};
    cfg.gridDim  = dim3((unsigned)nb2, 1, 1);
    cfg.blockDim = dim3(256, 1, 1);
    cfg.dynamicSmemBytes = 0;
    cfg.stream = 0;
    cudaLaunchAttribute attrs[1];
    attrs[0].id = cudaLaunchAttributeProgrammaticStreamSerialization;
    attrs[0].val.programmaticStreamSerializationAllowed = 1;
    cfg.attrs = attrs;
    cfg.numAttrs = 1;

    cudaLaunchKernelEx(&cfg, paths_fused_kernel,
                       paths, path_lens, path_mask,
                       (const float*)scores, b, edge_emb,
                       n_paths, max_len, nb2, out);
}

// round 9
// speedup vs baseline: 1.0645x; 1.0645x over previous
#include <cuda_runtime.h>
#include <math.h>

#define MAX_EDGES 100000
#define MAX_PART  512

__device__ float g_scores[MAX_EDGES];
__device__ float g_pmax[MAX_PART];
__device__ int   g_pidx[MAX_PART];
__device__ float g_psum[MAX_PART];
__device__ unsigned int g_ticket;   // zero-init; last block resets each run

// ---------------------------------------------------------------------------
// Kernel 1: s[e] = dot(edge_emb[e,:256], W)   [known-best: ~18.5us, 32 regs]
// ---------------------------------------------------------------------------
__global__ void __launch_bounds__(256) score_kernel(
        const float* __restrict__ emb,
        const float* __restrict__ W,
        float* __restrict__ s,
        int n_edges) {
    int warp = (blockIdx.x * blockDim.x + threadIdx.x) >> 5;
    int lane = threadIdx.x & 31;
    int e0 = warp * 2;

    if (e0 < n_edges) {
        const float4* w = reinterpret_cast<const float4*>(W);
        float4 w0 = __ldg(&w[lane * 2]);
        float4 w1 = __ldg(&w[lane * 2 + 1]);

        const float4* p0 = reinterpret_cast<const float4*>(emb + (size_t)e0 * 256);
        const float4* p1 = p0 + 64;

        float4 a0 = p0[lane * 2];
        float4 a1 = p0[lane * 2 + 1];
        float4 b0 = p1[lane * 2];
        float4 b1 = p1[lane * 2 + 1];

        float accA = a0.x*w0.x + a0.y*w0.y + a0.z*w0.z + a0.w*w0.w
                   + a1.x*w1.x + a1.y*w1.y + a1.z*w1.z + a1.w*w1.w;
        float accB = b0.x*w0.x + b0.y*w0.y + b0.z*w0.z + b0.w*w0.w
                   + b1.x*w1.x + b1.y*w1.y + b1.z*w1.z + b1.w*w1.w;

        #pragma unroll
        for (int o = 16; o; o >>= 1) {
            accA += __shfl_xor_sync(0xFFFFFFFFu, accA, o);
            accB += __shfl_xor_sync(0xFFFFFFFFu, accB, o);
        }

        if (lane == 0) {
            s[e0] = accA;
            if (e0 + 1 < n_edges) s[e0 + 1] = accB;
        }
    }

    cudaTriggerProgrammaticLaunchCompletion();
}

// ---------------------------------------------------------------------------
// Kernel 2 (fused, PDL secondary): FOUR threads per path.
// Each quad-thread loads one int4 of the path row (coalesced) and gathers
// <=4 scores with predicated loads (no excess traffic). Quad shuffle-reduce,
// then per-block flash-softmax partials; last ticket block finalizes.
// 313 blocks -> ~17 warps/SM for the latency-bound gather (vs 4.3 before).
// out: [0]=p, [1]=logprob, [2..257]=z[p]
// ---------------------------------------------------------------------------
__global__ void __launch_bounds__(256) paths_fused_kernel(
        const int* __restrict__ paths,
        const int* __restrict__ path_lens,
        const int* __restrict__ path_mask,
        const float* __restrict__ s,
        const float* __restrict__ b,
        const float* __restrict__ emb,
        int n_paths, int max_len, int n_blocks,
        float* __restrict__ out) {
    __shared__ float smax[256];
    __shared__ int   sidx[256];
    __shared__ float ssum[256];
    __shared__ int   s_is_last;

    int t    = threadIdx.x;
    int gid  = blockIdx.x * 256 + t;
    int quad = gid >> 2;          // path index
    int sub  = gid & 3;           // which int4 of the row
    bool live = (quad < n_paths);

    // ---- preamble: score-independent loads (overlap primary via PDL) ----
    int4 r = make_int4(0, 0, 0, 0);
    int  my_len = 1, my_mask = 0;
    float bias = 0.0f;
    if (live) {
        const int4* row = reinterpret_cast<const int4*>(paths + (size_t)quad * max_len);
        r = row[sub];                       // 4 threads cover the 64B row
        my_len  = path_lens[quad] + 1;
        my_mask = path_mask[quad];
        bias    = b[0];
    }

    cudaGridDependencySynchronize();        // scores ready

    // ---- gather <=4 scores, predicated (skipped loads issue nothing) ----
    float partial = 0.0f;
    if (live) {
        int base = sub * 4;
        float v0 = 0.0f, v1 = 0.0f, v2 = 0.0f, v3 = 0.0f;
        if (base + 0 < my_len) v0 = s[r.x];
        if (base + 1 < my_len) v1 = s[r.y];
        if (base + 2 < my_len) v2 = s[r.z];
        if (base + 3 < my_len) v3 = s[r.w];
        partial = (v0 + v1) + (v2 + v3);
    }

    // quad reduce (lanes 4k..4k+3)
    partial += __shfl_xor_sync(0xFFFFFFFFu, partial, 1);
    partial += __shfl_xor_sync(0xFFFFFFFFu, partial, 2);

    float logit = -INFINITY;
    int   idx   = 0x7FFFFFFF;
    bool leader = live && (sub == 0);
    if (leader) {
        logit = partial / (float)my_len + bias;
        if (my_mask == 0) logit = -1e9f;
        idx = quad;
    }

    // ---- block argmax (first-occurrence tiebreak) ----
    smax[t] = logit; sidx[t] = idx;
    __syncthreads();
    #pragma unroll
    for (int o = 128; o; o >>= 1) {
        if (t < o) {
            float v = smax[t + o]; int j = sidx[t + o];
            if (v > smax[t] || (v == smax[t] && j < sidx[t])) {
                smax[t] = v; sidx[t] = j;
            }
        }
        __syncthreads();
    }
    float bm = smax[0];

    // ---- block sumexp vs block max (quad leaders only contribute) ----
    float es = leader ? expf(logit - bm) : 0.0f;
    ssum[t] = es;
    __syncthreads();
    #pragma unroll
    for (int o = 128; o; o >>= 1) {
        if (t < o) ssum[t] += ssum[t + o];
        __syncthreads();
    }

    // ---- publish partials, draw ticket ----
    if (t == 0) {
        g_pmax[blockIdx.x] = bm;
        g_pidx[blockIdx.x] = sidx[0];
        g_psum[blockIdx.x] = ssum[0];
        __threadfence();
        unsigned rank = atomicAdd(&g_ticket, 1u);
        s_is_last = (rank == (unsigned)(n_blocks - 1));
    }
    __syncthreads();
    if (!s_is_last) return;

    // ===== last block: finalize =====
    __threadfence();

    // argmax over n_blocks (<=512) partials, 256-thread strided
    float m = -INFINITY;
    int   j = 0x7FFFFFFF;
    for (int k = t; k < n_blocks; k += 256) {
        float v = g_pmax[k]; int q = g_pidx[k];
        if (v > m || (v == m && q < j)) { m = v; j = q; }
    }
    smax[t] = m; sidx[t] = j;
    __syncthreads();
    #pragma unroll
    for (int o = 128; o; o >>= 1) {
        if (t < o) {
            float v = smax[t + o]; int k = sidx[t + o];
            if (v > smax[t] || (v == smax[t] && k < sidx[t])) {
                smax[t] = v; sidx[t] = k;
            }
        }
        __syncthreads();
    }
    float M = smax[0];
    int   p = sidx[0];
    __syncthreads();

    float e2 = 0.0f;
    for (int k = t; k < n_blocks; k += 256)
        e2 += g_psum[k] * expf(g_pmax[k] - M);
    ssum[t] = e2;
    __syncthreads();
    #pragma unroll
    for (int o = 128; o; o >>= 1) {
        if (t < o) ssum[t] += ssum[t + o];
        __syncthreads();
    }

    if (t == 0) {
        out[0] = (float)p;
        out[1] = -logf(ssum[0]);   // logits[p] == M
        g_ticket = 0;              // reset for next graph replay
    }

    // ---- z[p]: predicated-unroll ragged mean (MLP=len, no extra traffic) ----
    {
        int len = path_lens[p] + 1;
        const int4* row4 = reinterpret_cast<const int4*>(paths + (size_t)p * max_len);
        int4 q0 = row4[0], q1 = row4[1], q2 = row4[2], q3 = row4[3];
        int e[16] = { q0.x, q0.y, q0.z, q0.w, q1.x, q1.y, q1.z, q1.w,
                      q2.x, q2.y, q2.z, q2.w, q3.x, q3.y, q3.z, q3.w };
        float acc = 0.0f;
        #pragma unroll
        for (int k = 0; k < 16; ++k) {
            float v = 0.0f;
            if (k < len) v = emb[(size_t)e[k] * 256 + t];  // guarded, independent
            acc += v;
        }
        out[2 + t] = acc / (float)len;
    }
}

// ---------------------------------------------------------------------------
// Launch
// Inputs: edge_emb f32[100000,256], paths i32[20000,16], path_lens i32[20000],
//         path_mask i32[20000], W f32[1,256], b f32[1], deterministic i32[1]
// ---------------------------------------------------------------------------
extern "C" void kernel_launch(void* const* d_in, const int* in_sizes, int n_in,
                              void* d_out, int out_size) {
    const float* edge_emb  = (const float*)d_in[0];
    const int*   paths     = (const int*)d_in[1];
    const int*   path_lens = (const int*)d_in[2];
    const int*   path_mask = (const int*)d_in[3];
    const float* W         = (const float*)d_in[4];
    const float* b         = (const float*)d_in[5];

    int hidden  = in_sizes[4];              // 256
    int n_edges = in_sizes[0] / hidden;     // 100000
    int n_paths = in_sizes[2];              // 20000
    int max_len = in_sizes[1] / n_paths;    // 16

    float* out = (float*)d_out;

    float* scores; cudaGetSymbolAddress((void**)&scores, g_scores);

    // K1: 2 edges per warp, 8 warps per block (known-best config)
    {
        int edges_per_block = 16;
        int blocks = (n_edges + edges_per_block - 1) / edges_per_block;
        score_kernel<<<blocks, 256>>>(edge_emb, W, scores, n_edges);
    }

    // K2 fused: 4 threads per path -> 313 blocks of 256, PDL secondary
    int nb2 = (n_paths * 4 + 255) / 256;    // 313

    cudaLaunchConfig_t cfg = {};
    cfg.gridDim  = dim3((unsigned)nb2, 1, 1);
    cfg.blockDim = dim3(256, 1, 1);
    cfg.dynamicSmemBytes = 0;
    cfg.stream = 0;
    cudaLaunchAttribute attrs[1];
    attrs[0].id = cudaLaunchAttributeProgrammaticStreamSerialization;
    attrs[0].val.programmaticStreamSerializationAllowed = 1;
    cfg.attrs = attrs;
    cfg.numAttrs = 1;

    cudaLaunchKernelEx(&cfg, paths_fused_kernel,
                       paths, path_lens, path_mask,
                       (const float*)scores, b, edge_emb,
                       n_paths, max_len, nb2, out);
}

// round 10
// speedup vs baseline: 1.1348x; 1.0660x over previous
#include <cuda_runtime.h>
#include <math.h>

#define MAX_EDGES 100000
#define MAX_PART  256

__device__ float g_scores[MAX_EDGES];
__device__ float g_pmax[MAX_PART];
__device__ int   g_pidx[MAX_PART];
__device__ float g_psum[MAX_PART];
__device__ unsigned int g_ticket;   // zero-init; last block resets each run

// ---------------------------------------------------------------------------
// Kernel 1: s[e] = dot(edge_emb[e,:256], W)
// W staged through shared memory (1 KB, loaded once per block) -> zero L1tex
// wavefronts for weights (was 16/warp, half the total). Lane mapping
// {lane, lane+32} keeps every data LDG.128 at the 4-wavefront minimum.
// ---------------------------------------------------------------------------
__global__ void __launch_bounds__(256) score_kernel(
        const float* __restrict__ emb,
        const float* __restrict__ W,
        float* __restrict__ s,
        int n_edges) {
    __shared__ float4 sw[64];          // 256 floats = 1 KB

    int t    = threadIdx.x;
    int lane = t & 31;
    int warp = (blockIdx.x * blockDim.x + t) >> 5;
    int e0 = warp * 2;

    if (t < 64) sw[t] = reinterpret_cast<const float4*>(W)[t];
    __syncthreads();

    if (e0 < n_edges) {
        float4 w0 = sw[lane];          // conflict-free LDS.128
        float4 w1 = sw[lane + 32];

        const float4* p0 = reinterpret_cast<const float4*>(emb + (size_t)e0 * 256);
        const float4* p1 = p0 + 64;

        float4 a0 = p0[lane];
        float4 a1 = p0[lane + 32];
        float4 b0 = p1[lane];
        float4 b1 = p1[lane + 32];

        float accA = a0.x*w0.x + a0.y*w0.y + a0.z*w0.z + a0.w*w0.w
                   + a1.x*w1.x + a1.y*w1.y + a1.z*w1.z + a1.w*w1.w;
        float accB = b0.x*w0.x + b0.y*w0.y + b0.z*w0.z + b0.w*w0.w
                   + b1.x*w1.x + b1.y*w1.y + b1.z*w1.z + b1.w*w1.w;

        #pragma unroll
        for (int o = 16; o; o >>= 1) {
            accA += __shfl_xor_sync(0xFFFFFFFFu, accA, o);
            accB += __shfl_xor_sync(0xFFFFFFFFu, accB, o);
        }

        if (lane == 0) {
            s[e0] = accA;
            if (e0 + 1 < n_edges) s[e0 + 1] = accB;
        }
    }

    cudaTriggerProgrammaticLaunchCompletion();
}

// ---------------------------------------------------------------------------
// Kernel 2 (fused, PDL secondary) — unchanged from the 25.06us best (R7).
// Logits + flash-softmax partials; last ticket block finalizes p/logprob/z[p].
// out: [0]=p, [1]=logprob, [2..257]=z[p]
// ---------------------------------------------------------------------------
__global__ void __launch_bounds__(256) paths_fused_kernel(
        const int* __restrict__ paths,
        const int* __restrict__ path_lens,
        const int* __restrict__ path_mask,
        const float* __restrict__ s,
        const float* __restrict__ b,
        const float* __restrict__ emb,
        int n_paths, int max_len, int n_blocks,
        float* __restrict__ out) {
    __shared__ float smax[256];
    __shared__ int   sidx[256];
    __shared__ float ssum[256];
    __shared__ int   s_is_last;

    int t = threadIdx.x;
    int i = blockIdx.x * 256 + t;
    bool live = (i < n_paths);

    // preamble: score-independent loads (overlap primary via PDL)
    int4 r0 = make_int4(0,0,0,0), r1 = r0, r2 = r0, r3 = r0;
    int  my_len = 1, my_mask = 0;
    float bias = 0.0f;
    if (live) {
        const int4* row = reinterpret_cast<const int4*>(paths + (size_t)i * max_len);
        r0 = row[0]; r1 = row[1]; r2 = row[2]; r3 = row[3];
        my_len  = path_lens[i] + 1;
        my_mask = path_mask[i];
        bias    = b[0];
    }

    cudaGridDependencySynchronize();   // scores ready

    float logit = -INFINITY;
    int   idx   = 0x7FFFFFFF;
    if (live) {
        int e[16] = { r0.x, r0.y, r0.z, r0.w, r1.x, r1.y, r1.z, r1.w,
                      r2.x, r2.y, r2.z, r2.w, r3.x, r3.y, r3.z, r3.w };
        float sum = 0.0f;
        #pragma unroll
        for (int j = 0; j < 16; ++j)
            if (j < my_len) sum += s[e[j]];
        logit = sum / (float)my_len + bias;
        if (my_mask == 0) logit = -1e9f;
        idx = i;
    }

    // block argmax (first-occurrence tiebreak)
    smax[t] = logit; sidx[t] = idx;
    __syncthreads();
    #pragma unroll
    for (int o = 128; o; o >>= 1) {
        if (t < o) {
            float v = smax[t + o]; int j = sidx[t + o];
            if (v > smax[t] || (v == smax[t] && j < sidx[t])) {
                smax[t] = v; sidx[t] = j;
            }
        }
        __syncthreads();
    }
    float bm = smax[0];

    float es = live ? expf(logit - bm) : 0.0f;
    ssum[t] = es;
    __syncthreads();
    #pragma unroll
    for (int o = 128; o; o >>= 1) {
        if (t < o) ssum[t] += ssum[t + o];
        __syncthreads();
    }

    if (t == 0) {
        g_pmax[blockIdx.x] = bm;
        g_pidx[blockIdx.x] = sidx[0];
        g_psum[blockIdx.x] = ssum[0];
        __threadfence();
        unsigned rank = atomicAdd(&g_ticket, 1u);
        s_is_last = (rank == (unsigned)(n_blocks - 1));
    }
    __syncthreads();
    if (!s_is_last) return;

    // ===== last block: finalize =====
    __threadfence();

    float m = (t < n_blocks) ? g_pmax[t] : -INFINITY;
    int   j = (t < n_blocks) ? g_pidx[t] : 0x7FFFFFFF;
    smax[t] = m; sidx[t] = j;
    __syncthreads();
    #pragma unroll
    for (int o = 128; o; o >>= 1) {
        if (t < o) {
            float v = smax[t + o]; int k = sidx[t + o];
            if (v > smax[t] || (v == smax[t] && k < sidx[t])) {
                smax[t] = v; sidx[t] = k;
            }
        }
        __syncthreads();
    }
    float M = smax[0];
    int   p = sidx[0];
    __syncthreads();

    float e2 = (t < n_blocks) ? g_psum[t] * expf(g_pmax[t] - M) : 0.0f;
    ssum[t] = e2;
    __syncthreads();
    #pragma unroll
    for (int o = 128; o; o >>= 1) {
        if (t < o) ssum[t] += ssum[t + o];
        __syncthreads();
    }

    if (t == 0) {
        out[0] = (float)p;
        out[1] = -logf(ssum[0]);   // logits[p] == M
        g_ticket = 0;              // reset for next graph replay
    }

    // z[p]: guarded-unroll ragged mean (parallel loads, no excess traffic)
    {
        int len = path_lens[p] + 1;
        const int4* row4 = reinterpret_cast<const int4*>(paths + (size_t)p * max_len);
        int4 q0 = row4[0], q1 = row4[1], q2 = row4[2], q3 = row4[3];
        int e[16] = { q0.x, q0.y, q0.z, q0.w, q1.x, q1.y, q1.z, q1.w,
                      q2.x, q2.y, q2.z, q2.w, q3.x, q3.y, q3.z, q3.w };
        float acc = 0.0f;
        #pragma unroll
        for (int k = 0; k < 16; ++k) {
            float v = 0.0f;
            if (k < len) v = emb[(size_t)e[k] * 256 + t];
            acc += v;
        }
        out[2 + t] = acc / (float)len;
    }
}

// ---------------------------------------------------------------------------
// Launch
// Inputs: edge_emb f32[100000,256], paths i32[20000,16], path_lens i32[20000],
//         path_mask i32[20000], W f32[1,256], b f32[1], deterministic i32[1]
// ---------------------------------------------------------------------------
extern "C" void kernel_launch(void* const* d_in, const int* in_sizes, int n_in,
                              void* d_out, int out_size) {
    const float* edge_emb  = (const float*)d_in[0];
    const int*   paths     = (const int*)d_in[1];
    const int*   path_lens = (const int*)d_in[2];
    const int*   path_mask = (const int*)d_in[3];
    const float* W         = (const float*)d_in[4];
    const float* b         = (const float*)d_in[5];

    int hidden  = in_sizes[4];              // 256
    int n_edges = in_sizes[0] / hidden;     // 100000
    int n_paths = in_sizes[2];              // 20000
    int max_len = in_sizes[1] / n_paths;    // 16

    float* out = (float*)d_out;

    float* scores; cudaGetSymbolAddress((void**)&scores, g_scores);

    // K1: 2 edges per warp, 8 warps per block; W staged via smem
    {
        int edges_per_block = 16;
        int blocks = (n_edges + edges_per_block - 1) / edges_per_block;
        score_kernel<<<blocks, 256>>>(edge_emb, W, scores, n_edges);
    }

    // K2 fused, PDL secondary (unchanged best config)
    int nb2 = (n_paths + 255) / 256;        // 79

    cudaLaunchConfig_t cfg = {};
    cfg.gridDim  = dim3((unsigned)nb2, 1, 1);
    cfg.blockDim = dim3(256, 1, 1);
    cfg.dynamicSmemBytes = 0;
    cfg.stream = 0;
    cudaLaunchAttribute attrs[1];
    attrs[0].id = cudaLaunchAttributeProgrammaticStreamSerialization;
    attrs[0].val.programmaticStreamSerializationAllowed = 1;
    cfg.attrs = attrs;
    cfg.numAttrs = 1;

    cudaLaunchKernelEx(&cfg, paths_fused_kernel,
                       paths, path_lens, path_mask,
                       (const float*)scores, b, edge_emb,
                       n_paths, max_len, nb2, out);
}

// round 11
// speedup vs baseline: 1.1977x; 1.0555x over previous
#include <cuda_runtime.h>
#include <math.h>

#define MAX_EDGES 100000

__device__ float g_scores[MAX_EDGES];
__device__ unsigned long long g_key;    // [sortable(logit):32 | ~idx:32], init 0
__device__ float g_sumexp;              // sum exp(logit), init 0
__device__ unsigned int g_ticket;       // init 0; finalize resets all three

// ---------------------------------------------------------------------------
// Kernel 1: s[e] = dot(edge_emb[e,:256], W)   [frozen R10 winner]
// W staged via smem (no L1tex wavefronts for weights); lane map {lane,lane+32}
// keeps each data LDG.128 at the 4-wavefront minimum.
// ---------------------------------------------------------------------------
__global__ void __launch_bounds__(256) score_kernel(
        const float* __restrict__ emb,
        const float* __restrict__ W,
        float* __restrict__ s,
        int n_edges) {
    __shared__ float4 sw[64];

    int t    = threadIdx.x;
    int lane = t & 31;
    int warp = (blockIdx.x * blockDim.x + t) >> 5;
    int e0 = warp * 2;

    if (t < 64) sw[t] = reinterpret_cast<const float4*>(W)[t];
    __syncthreads();

    if (e0 < n_edges) {
        float4 w0 = sw[lane];
        float4 w1 = sw[lane + 32];

        const float4* p0 = reinterpret_cast<const float4*>(emb + (size_t)e0 * 256);
        const float4* p1 = p0 + 64;

        float4 a0 = p0[lane];
        float4 a1 = p0[lane + 32];
        float4 b0 = p1[lane];
        float4 b1 = p1[lane + 32];

        float accA = a0.x*w0.x + a0.y*w0.y + a0.z*w0.z + a0.w*w0.w
                   + a1.x*w1.x + a1.y*w1.y + a1.z*w1.z + a1.w*w1.w;
        float accB = b0.x*w0.x + b0.y*w0.y + b0.z*w0.z + b0.w*w0.w
                   + b1.x*w1.x + b1.y*w1.y + b1.z*w1.z + b1.w*w1.w;

        #pragma unroll
        for (int o = 16; o; o >>= 1) {
            accA += __shfl_xor_sync(0xFFFFFFFFu, accA, o);
            accB += __shfl_xor_sync(0xFFFFFFFFu, accB, o);
        }

        if (lane == 0) {
            s[e0] = accA;
            if (e0 + 1 < n_edges) s[e0 + 1] = accB;
        }
    }

    cudaTriggerProgrammaticLaunchCompletion();
}

// sortable encoding: preserves float order as unsigned order (bijective)
__device__ __forceinline__ unsigned int f2sortable(float f) {
    unsigned int u = __float_as_uint(f);
    return (u & 0x80000000u) ? ~u : (u | 0x80000000u);
}
__device__ __forceinline__ float sortable2f(unsigned int u) {
    u = (u & 0x80000000u) ? (u & 0x7FFFFFFFu) : ~u;
    return __uint_as_float(u);
}

// ---------------------------------------------------------------------------
// Kernel 2 (fused, PDL secondary): no block reductions, no partial arrays.
// Each thread: logit -> exp(logit) (fixed reference C=0; logits are O(1) so
// no overflow, masked -1e9 underflows to exactly 0 like the reference).
// Warp shuffle-reduce (argmax key, sumexp), 1 atomicMax + 1 atomicAdd per
// warp. Last ticket block decodes p and l_p from g_key, writes out, z[p].
// out: [0]=p, [1]=logprob, [2..257]=z[p]
// ---------------------------------------------------------------------------
__global__ void __launch_bounds__(256) paths_fused_kernel(
        const int* __restrict__ paths,
        const int* __restrict__ path_lens,
        const int* __restrict__ path_mask,
        const float* __restrict__ s,
        const float* __restrict__ b,
        const float* __restrict__ emb,
        int n_paths, int max_len, int n_blocks,
        float* __restrict__ out) {
    __shared__ int s_is_last;

    int t = threadIdx.x;
    int i = blockIdx.x * 256 + t;
    bool live = (i < n_paths);

    // preamble: score-independent loads (overlap primary via PDL)
    int4 r0 = make_int4(0,0,0,0), r1 = r0, r2 = r0, r3 = r0;
    int  my_len = 1, my_mask = 0;
    float bias = 0.0f;
    if (live) {
        const int4* row = reinterpret_cast<const int4*>(paths + (size_t)i * max_len);
        r0 = row[0]; r1 = row[1]; r2 = row[2]; r3 = row[3];
        my_len  = path_lens[i] + 1;
        my_mask = path_mask[i];
        bias    = b[0];
    }

    cudaGridDependencySynchronize();   // scores ready

    float logit = -1e9f;               // dead threads contribute exp->0, idx loses
    int   idx   = 0x7FFFFFFF;
    if (live) {
        int e[16] = { r0.x, r0.y, r0.z, r0.w, r1.x, r1.y, r1.z, r1.w,
                      r2.x, r2.y, r2.z, r2.w, r3.x, r3.y, r3.z, r3.w };
        float sum = 0.0f;
        #pragma unroll
        for (int j = 0; j < 16; ++j)
            if (j < my_len) sum += s[e[j]];
        logit = sum / (float)my_len + bias;
        if (my_mask == 0) logit = -1e9f;
        idx = i;
    }

    // key: larger logit wins; tie -> smaller idx wins (first occurrence)
    unsigned long long key =
        ((unsigned long long)f2sortable(logit) << 32) |
        (unsigned long long)(0xFFFFFFFFu - (unsigned)idx);
    float ex = live ? expf(logit) : 0.0f;   // exp(-1e9) == 0 exactly

    // warp reduce: max key + sum exp
    #pragma unroll
    for (int o = 16; o; o >>= 1) {
        unsigned long long ok = __shfl_xor_sync(0xFFFFFFFFu, key, o);
        if (ok > key) key = ok;
        ex += __shfl_xor_sync(0xFFFFFFFFu, ex, o);
    }

    if ((t & 31) == 0) {
        atomicMax(&g_key, key);
        if (ex > 0.0f) atomicAdd(&g_sumexp, ex);
    }

    __syncthreads();                    // all warps of this block published
    if (t == 0) {
        __threadfence();
        unsigned rank = atomicAdd(&g_ticket, 1u);
        s_is_last = (rank == (unsigned)(n_blocks - 1));
    }
    __syncthreads();
    if (!s_is_last) return;

    // ===== last block: finalize =====
    __threadfence();

    unsigned long long fk = g_key;
    float S   = g_sumexp;
    int   p   = (int)(0xFFFFFFFFu - (unsigned)(fk & 0xFFFFFFFFull));
    float l_p = sortable2f((unsigned)(fk >> 32));

    if (t == 0) {
        out[0] = (float)p;
        out[1] = l_p - logf(S);
        g_key = 0ull;                   // reset for next graph replay
        g_sumexp = 0.0f;
        g_ticket = 0;
    }

    // z[p]: guarded-unroll ragged mean (parallel independent loads)
    {
        int len = path_lens[p] + 1;
        const int4* row4 = reinterpret_cast<const int4*>(paths + (size_t)p * max_len);
        int4 q0 = row4[0], q1 = row4[1], q2 = row4[2], q3 = row4[3];
        int e[16] = { q0.x, q0.y, q0.z, q0.w, q1.x, q1.y, q1.z, q1.w,
                      q2.x, q2.y, q2.z, q2.w, q3.x, q3.y, q3.z, q3.w };
        float acc = 0.0f;
        #pragma unroll
        for (int k = 0; k < 16; ++k) {
            float v = 0.0f;
            if (k < len) v = emb[(size_t)e[k] * 256 + t];
            acc += v;
        }
        out[2 + t] = acc / (float)len;
    }
}

// ---------------------------------------------------------------------------
// Launch
// Inputs: edge_emb f32[100000,256], paths i32[20000,16], path_lens i32[20000],
//         path_mask i32[20000], W f32[1,256], b f32[1], deterministic i32[1]
// ---------------------------------------------------------------------------
extern "C" void kernel_launch(void* const* d_in, const int* in_sizes, int n_in,
                              void* d_out, int out_size) {
    const float* edge_emb  = (const float*)d_in[0];
    const int*   paths     = (const int*)d_in[1];
    const int*   path_lens = (const int*)d_in[2];
    const int*   path_mask = (const int*)d_in[3];
    const float* W         = (const float*)d_in[4];
    const float* b         = (const float*)d_in[5];

    int hidden  = in_sizes[4];              // 256
    int n_edges = in_sizes[0] / hidden;     // 100000
    int n_paths = in_sizes[2];              // 20000
    int max_len = in_sizes[1] / n_paths;    // 16

    float* out = (float*)d_out;

    float* scores; cudaGetSymbolAddress((void**)&scores, g_scores);

    // K1: frozen winner (2 edges/warp, smem W)
    {
        int edges_per_block = 16;
        int blocks = (n_edges + edges_per_block - 1) / edges_per_block;
        score_kernel<<<blocks, 256>>>(edge_emb, W, scores, n_edges);
    }

    // K2 fused, PDL secondary
    int nb2 = (n_paths + 255) / 256;        // 79

    cudaLaunchConfig_t cfg = {};
    cfg.gridDim  = dim3((unsigned)nb2, 1, 1);
    cfg.blockDim = dim3(256, 1, 1);
    cfg.dynamicSmemBytes = 0;
    cfg.stream = 0;
    cudaLaunchAttribute attrs[1];
    attrs[0].id = cudaLaunchAttributeProgrammaticStreamSerialization;
    attrs[0].val.programmaticStreamSerializationAllowed = 1;
    cfg.attrs = attrs;
    cfg.numAttrs = 1;

    cudaLaunchKernelEx(&cfg, paths_fused_kernel,
                       paths, path_lens, path_mask,
                       (const float*)scores, b, edge_emb,
                       n_paths, max_len, nb2, out);
}